// round 1
// baseline (speedup 1.0000x reference)
#include <cuda_runtime.h>
#include <cuda_bf16.h>

#define S 8192
#define H 2048

__device__ float g_u[H];        // u[k] = sum_j w[j] * W_att[j, H+k]
__device__ float g_scores[S];   // scores[s] = enc[s] . u

// ---------------------------------------------------------------------------
// Kernel 0: zero the u accumulator (atomic target)
// ---------------------------------------------------------------------------
__global__ void zero_u_kernel() {
    int i = blockIdx.x * blockDim.x + threadIdx.x;
    if (i < H) g_u[i] = 0.0f;
}

// ---------------------------------------------------------------------------
// Kernel 1: u[k] = sum_j w[j] * W_att[j*2H + H + k]
// Grid: 512 blocks of 256 threads. Block b: k-tile = (b%8)*256, j-chunk = (b/8)*32.
// Each thread accumulates 32 rows in a register, then one atomicAdd.
// Per-j access: 256 threads read 1KB contiguous -> fully coalesced.
// ---------------------------------------------------------------------------
__global__ void __launch_bounds__(256) u_kernel(const float* __restrict__ W_att,
                                                const float* __restrict__ w) {
    const int k = (blockIdx.x & 7) * 256 + threadIdx.x;
    const int j0 = (blockIdx.x >> 3) * 32;
    const float* base = W_att + (size_t)j0 * (2 * H) + H + k;
    float acc = 0.0f;
#pragma unroll 8
    for (int jj = 0; jj < 32; jj++) {
        acc += w[j0 + jj] * base[(size_t)jj * (2 * H)];
    }
    atomicAdd(&g_u[k], acc);
}

// ---------------------------------------------------------------------------
// Kernel 2: scores[s] = dot(enc[s], u). One 256-thread block per row.
// Each thread: 8 consecutive floats (2x float4), warp+smem reduce.
// ---------------------------------------------------------------------------
__global__ void __launch_bounds__(256) score_kernel(const float* __restrict__ enc) {
    const int s = blockIdx.x;
    const int t = threadIdx.x;
    const float4* e = reinterpret_cast<const float4*>(enc + (size_t)s * H) + t * 2;
    const float4* u = reinterpret_cast<const float4*>(g_u) + t * 2;

    float4 e0 = e[0], e1 = e[1];
    float4 u0 = u[0], u1 = u[1];
    float acc = e0.x * u0.x + e0.y * u0.y + e0.z * u0.z + e0.w * u0.w
              + e1.x * u1.x + e1.y * u1.y + e1.z * u1.z + e1.w * u1.w;

    // warp reduce
#pragma unroll
    for (int off = 16; off > 0; off >>= 1)
        acc += __shfl_down_sync(0xffffffffu, acc, off);

    __shared__ float sm[8];
    const int lane = t & 31, wid = t >> 5;
    if (lane == 0) sm[wid] = acc;
    __syncthreads();
    if (wid == 0) {
        float v = (lane < 8) ? sm[lane] : 0.0f;
#pragma unroll
        for (int off = 4; off > 0; off >>= 1)
            v += __shfl_down_sync(0xffffffffu, v, off);
        if (lane == 0) g_scores[s] = v;
    }
}

// ---------------------------------------------------------------------------
// Kernel 3: softmax over the 8192 scores, single block of 1024 threads.
// ---------------------------------------------------------------------------
__global__ void __launch_bounds__(1024) softmax_kernel(float* __restrict__ out) {
    const int t = threadIdx.x;
    float v[8];
#pragma unroll
    for (int i = 0; i < 8; i++) v[i] = g_scores[t + i * 1024];

    // --- block max ---
    float mx = v[0];
#pragma unroll
    for (int i = 1; i < 8; i++) mx = fmaxf(mx, v[i]);
#pragma unroll
    for (int off = 16; off > 0; off >>= 1)
        mx = fmaxf(mx, __shfl_xor_sync(0xffffffffu, mx, off));

    __shared__ float sm[32];
    __shared__ float s_bcast;
    const int lane = t & 31, wid = t >> 5;
    if (lane == 0) sm[wid] = mx;
    __syncthreads();
    if (wid == 0) {
        float m = sm[lane];  // 32 warps -> all lanes valid
#pragma unroll
        for (int off = 16; off > 0; off >>= 1)
            m = fmaxf(m, __shfl_xor_sync(0xffffffffu, m, off));
        if (lane == 0) s_bcast = m;
    }
    __syncthreads();
    mx = s_bcast;

    // --- exp + block sum ---
    float e[8];
    float sum = 0.0f;
#pragma unroll
    for (int i = 0; i < 8; i++) {
        e[i] = expf(v[i] - mx);
        sum += e[i];
    }
#pragma unroll
    for (int off = 16; off > 0; off >>= 1)
        sum += __shfl_xor_sync(0xffffffffu, sum, off);
    if (lane == 0) sm[wid] = sum;
    __syncthreads();
    if (wid == 0) {
        float sv = sm[lane];
#pragma unroll
        for (int off = 16; off > 0; off >>= 1)
            sv += __shfl_xor_sync(0xffffffffu, sv, off);
        if (lane == 0) s_bcast = sv;
    }
    __syncthreads();
    const float inv = 1.0f / s_bcast;

#pragma unroll
    for (int i = 0; i < 8; i++) out[t + i * 1024] = e[i] * inv;
}

// ---------------------------------------------------------------------------
// Inputs (metadata order): encoder_outputs (S*1*H), hidden (H),
//                          W_att (H*2H), b_att (H), w (1*H)
// hidden and b_att drop out (softmax shift invariance).
// ---------------------------------------------------------------------------
extern "C" void kernel_launch(void* const* d_in, const int* in_sizes, int n_in,
                              void* d_out, int out_size) {
    const float* enc   = (const float*)d_in[0];
    const float* W_att = (const float*)d_in[2];
    const float* w     = (const float*)d_in[4];
    float* out = (float*)d_out;

    zero_u_kernel<<<2, 1024>>>();
    u_kernel<<<512, 256>>>(W_att, w);
    score_kernel<<<S, 256>>>(enc);
    softmax_kernel<<<1, 1024>>>(out);
}

// round 2
// speedup vs baseline: 1.1372x; 1.1372x over previous
#include <cuda_runtime.h>
#include <cuda_bf16.h>

#define S 8192
#define H 2048

// All __device__ globals are zero-initialized at module load.
// The LAST kernel of each launch resets them to zero-state for the next
// replay, so every invocation (correctness call + every graph replay) sees
// identical initial state.
__device__ float    g_u[H];          // u[k] = sum_j w[j] * W_att[j, H+k]  (needs 0 at entry)
__device__ float    g_scores[S];     // overwritten each run
__device__ unsigned g_max_key;       // ordered-uint encoding of max score (0 == -inf-most key)
__device__ float    g_psum[32];      // overwritten each run

// Ordered-uint encoding: monotonic map float -> uint so atomicMax works.
__device__ __forceinline__ unsigned f2key(float f) {
    unsigned u = __float_as_uint(f);
    return (u & 0x80000000u) ? ~u : (u | 0x80000000u);
}
__device__ __forceinline__ float key2f(unsigned k) {
    return (k & 0x80000000u) ? __uint_as_float(k ^ 0x80000000u)
                             : __uint_as_float(~k);
}

// ---------------------------------------------------------------------------
// Kernel 1: u[k] = sum_j w[j] * W_att[j*2H + H + k]
// 512 blocks = 8 k-tiles x 64 j-chunks of 32 rows. One atomicAdd per thread.
// g_u is zero at entry (module init / end-of-previous-run reset).
// ---------------------------------------------------------------------------
__global__ void __launch_bounds__(256) u_kernel(const float* __restrict__ W_att,
                                                const float* __restrict__ w) {
    const int k  = (blockIdx.x & 7) * 256 + threadIdx.x;
    const int j0 = (blockIdx.x >> 3) * 32;
    const float* base = W_att + (size_t)j0 * (2 * H) + H + k;
    float acc = 0.0f;
#pragma unroll 8
    for (int jj = 0; jj < 32; jj++)
        acc += w[j0 + jj] * base[(size_t)jj * (2 * H)];
    atomicAdd(&g_u[k], acc);
}

// ---------------------------------------------------------------------------
// Kernel 2: scores[s] = dot(enc[s], u) for 8 rows per block, plus global max.
// Each thread keeps its 8-float u-slice in registers; 16 independent LDG.128
// per thread across the 8 rows for high MLP. 1 atomicMax per block.
// ---------------------------------------------------------------------------
#define ROWS_PER_BLK 8
__global__ void __launch_bounds__(256) score_kernel(const float* __restrict__ enc) {
    const int t    = threadIdx.x;
    const int row0 = blockIdx.x * ROWS_PER_BLK;

    const float4* up = reinterpret_cast<const float4*>(g_u) + t * 2;
    const float4 u0 = up[0], u1 = up[1];

    float acc[ROWS_PER_BLK];
#pragma unroll
    for (int r = 0; r < ROWS_PER_BLK; r++) {
        const float4* e = reinterpret_cast<const float4*>(
                              enc + (size_t)(row0 + r) * H) + t * 2;
        const float4 e0 = e[0], e1 = e[1];
        acc[r] = e0.x * u0.x + e0.y * u0.y + e0.z * u0.z + e0.w * u0.w
               + e1.x * u1.x + e1.y * u1.y + e1.z * u1.z + e1.w * u1.w;
    }

    // Per-warp reduce each row, stage to smem.
    __shared__ float sm[8][ROWS_PER_BLK];   // [warp][row]
    const int lane = t & 31, wid = t >> 5;
#pragma unroll
    for (int r = 0; r < ROWS_PER_BLK; r++) {
        float v = acc[r];
#pragma unroll
        for (int off = 16; off > 0; off >>= 1)
            v += __shfl_down_sync(0xffffffffu, v, off);
        if (lane == 0) sm[wid][r] = v;
    }
    __syncthreads();

    // Warp 0: lanes 0..7 finish one row each, then one atomicMax per block.
    if (wid == 0) {
        float v = 0.0f;
        if (lane < ROWS_PER_BLK) {
#pragma unroll
            for (int w8 = 0; w8 < 8; w8++) v += sm[w8][lane];
            g_scores[row0 + lane] = v;
        }
        float m = (lane < ROWS_PER_BLK) ? v : -3.0e38f;
#pragma unroll
        for (int off = 16; off > 0; off >>= 1)
            m = fmaxf(m, __shfl_xor_sync(0xffffffffu, m, off));
        if (lane == 0) atomicMax(&g_max_key, f2key(m));
    }
}

// ---------------------------------------------------------------------------
// Kernel 3: e[s] = exp(score[s] - max); per-block partial sums.
// 32 blocks x 256 threads = one score per thread; exp is spread over 32 SMs.
// Writes staged exp values directly into d_out.
// ---------------------------------------------------------------------------
__global__ void __launch_bounds__(256) exp_kernel(float* __restrict__ out) {
    const int s = blockIdx.x * 256 + threadIdx.x;
    const float mx = key2f(g_max_key);
    const float e = expf(g_scores[s] - mx);
    out[s] = e;

    float v = e;
#pragma unroll
    for (int off = 16; off > 0; off >>= 1)
        v += __shfl_down_sync(0xffffffffu, v, off);

    __shared__ float sm[8];
    const int lane = threadIdx.x & 31, wid = threadIdx.x >> 5;
    if (lane == 0) sm[wid] = v;
    __syncthreads();
    if (wid == 0) {
        float p = (lane < 8) ? sm[lane] : 0.0f;
#pragma unroll
        for (int off = 4; off > 0; off >>= 1)
            p += __shfl_down_sync(0xffffffffu, p, off);
        if (lane == 0) g_psum[blockIdx.x] = p;
    }
}

// ---------------------------------------------------------------------------
// Kernel 4: normalize out in place; each block redundantly sums the 32
// partials (no extra sync kernel). Also resets g_u and g_max_key for the
// next replay.
// ---------------------------------------------------------------------------
__global__ void __launch_bounds__(1024) norm_kernel(float* __restrict__ out) {
    const int t = threadIdx.x;
    __shared__ float s_inv;
    if (t < 32) {
        float p = g_psum[t];
#pragma unroll
        for (int off = 16; off > 0; off >>= 1)
            p += __shfl_xor_sync(0xffffffffu, p, off);
        if (t == 0) s_inv = 1.0f / p;
    }
    __syncthreads();
    const float inv = s_inv;
    const int s = blockIdx.x * 1024 + t;
    out[s] *= inv;

    // --- state reset for next replay ---
    if (blockIdx.x < 2) g_u[blockIdx.x * 1024 + t] = 0.0f;
    if (blockIdx.x == 2 && t == 0) g_max_key = 0u;
}

// ---------------------------------------------------------------------------
// Inputs (metadata order): encoder_outputs (S*1*H), hidden (H),
//                          W_att (H*2H), b_att (H), w (1*H)
// hidden / b_att / left half of W_att drop out (softmax shift invariance).
// ---------------------------------------------------------------------------
extern "C" void kernel_launch(void* const* d_in, const int* in_sizes, int n_in,
                              void* d_out, int out_size) {
    const float* enc   = (const float*)d_in[0];
    const float* W_att = (const float*)d_in[2];
    const float* w     = (const float*)d_in[4];
    float* out = (float*)d_out;

    u_kernel<<<512, 256>>>(W_att, w);
    score_kernel<<<S / ROWS_PER_BLK, 256>>>(enc);
    exp_kernel<<<32, 256>>>(out);
    norm_kernel<<<8, 1024>>>(out);
}